// round 17
// baseline (speedup 1.0000x reference)
#include <cuda_runtime.h>
#include <cstdint>

// Maxwell RNN: per-row linear recurrence. One warp = one row, each warp
// running a PRIVATE depth-3 cp.async pipeline; 8 warps per CTA so 4 CTAs
// (32 warps) fit per SM -> every row assigned to an SM is resident and
// issuing concurrently. No block barriers, no inter-warp coupling.
//
//   gamma_t = (1 - 0.5*dt)*gamma_{t-1} + 0.5*dt*eps_t,  gamma_{-1} = 0
//   sig_t   = 2.5*eps_t - gamma_{t-1}
// Per chunk of 256 elems (8/lane): sig_j = C_j - Pp_j*g (C/Pp in place),
// carry = P31*carry + Q31.

constexpr int Bn    = 4096;
constexpr int Tn    = 8192;
constexpr int TPB   = 256;
constexpr int WPB   = TPB / 32;            // 8 warps = 8 rows per block
constexpr int CHUNK = 256;                 // elements per warp-chunk
constexpr int EPT   = 8;                   // elements per lane
constexpr int NCH   = Tn / CHUNK;          // 32 chunks per row
constexpr int GRID  = Bn / WPB;            // 512 blocks
constexpr int D     = 3;                   // pipeline depth (stages)
constexpr int STAGE_B = 2048;              // 1KB eps + 1KB dt per stage

__device__ __forceinline__ uint32_t swz16(uint32_t u) {
    // XOR-swizzle 16B units within 128B rows: conflict-free LDS.128 reads
    return (u & ~7u) | ((u ^ (u >> 3)) & 7u);
}
__device__ __forceinline__ void cpasync16(uint32_t dst, const void* src) {
    asm volatile("cp.async.cg.shared.global [%0], [%1], 16;"
                 :: "r"(dst), "l"(src) : "memory");
}
__device__ __forceinline__ void cp_commit() {
    asm volatile("cp.async.commit_group;" ::: "memory");
}
template <int N>
__device__ __forceinline__ void cp_wait() {
    asm volatile("cp.async.wait_group %0;" :: "n"(N) : "memory");
}

__global__ void __launch_bounds__(TPB)
maxwell_cpasync_kernel(const float* __restrict__ eps, const float* __restrict__ dt,
                       float* __restrict__ out) {
    __shared__ __align__(16) char sm[WPB * D * STAGE_B];   // 48 KB

    const int lane = threadIdx.x & 31;
    const int wid  = threadIdx.x >> 5;

    // 32-bit element offset of this warp's row (33.5M < 2^32)
    const unsigned row0 = (blockIdx.x * WPB + wid) * (unsigned)Tn;

    char* warp_sm = sm + wid * (D * STAGE_B);
    // this lane's two 16B units per chunk (swizzled), fixed within a stage
    const uint32_t u0 = swz16(2 * lane) * 16;
    const uint32_t u1 = swz16(2 * lane + 1) * 16;
    const uint32_t g0 = 2 * lane * 16;         // matching global byte offsets
    const uint32_t g1 = g0 + 16;

    // ---- prologue: fill stages 0..D-1 (one commit group per chunk) ----
    #pragma unroll
    for (int c = 0; c < D; c++) {
        char* st = warp_sm + c * STAGE_B;
        uint32_t sE = (uint32_t)__cvta_generic_to_shared(st);
        uint32_t sD = sE + 1024;
        const char* gE = (const char*)(eps + row0 + c * CHUNK);
        const char* gD = (const char*)(dt  + row0 + c * CHUNK);
        cpasync16(sE + u0, gE + g0);
        cpasync16(sE + u1, gE + g1);
        cpasync16(sD + u0, gD + g0);
        cpasync16(sD + u1, gD + g1);
        cp_commit();
    }

    float carry = 0.0f;
    unsigned off = row0 + lane * EPT;          // this lane's output offset

    for (int c = 0; c < NCH; c++) {
        cp_wait<D - 1>();                      // oldest group (chunk c) done

        char* st = warp_sm + (c % D) * STAGE_B;
        const float4* pE = (const float4*)st;
        const float4* pD = (const float4*)(st + 1024);
        // swizzled, conflict-free LDS.128 reads of this lane's 8+8 floats
        float4 e0 = pE[u0 >> 4], e1 = pE[u1 >> 4];
        float4 d0 = pD[u0 >> 4], d1 = pD[u1 >> 4];

        // ---- refill this stage with chunk c+D; ALWAYS commit (group/chunk) ----
        if (c + D < NCH) {
            uint32_t sE = (uint32_t)__cvta_generic_to_shared(st);
            uint32_t sD = sE + 1024;
            const char* gE = (const char*)(eps + row0 + (c + D) * CHUNK);
            const char* gD = (const char*)(dt  + row0 + (c + D) * CHUNK);
            cpasync16(sE + u0, gE + g0);
            cpasync16(sE + u1, gE + g1);
            cpasync16(sD + u0, gD + g0);
            cpasync16(sD + u1, gD + g1);
        }
        cp_commit();

        float ee[EPT] = { e0.x, e0.y, e0.z, e0.w, e1.x, e1.y, e1.z, e1.w };
        float dd[EPT] = { d0.x, d0.y, d0.z, d0.w, d1.x, d1.y, d1.z, d1.w };

        // ---- local affine fold; rewrite (ee,dd) -> (C, Pp) in place ----
        float P = 1.0f, Q = 0.0f;
        #pragma unroll
        for (int j = 0; j < EPT; j++) {
            float e = ee[j];
            float d = dd[j];
            dd[j] = P;                          // Pp_j
            ee[j] = fmaf(2.5f, e, -Q);          // C_j
            float ad = 0.5f * d;
            float A  = 1.0f - ad;
            Q = fmaf(A, Q, ad * e);
            P = P * A;
        }

        // ---- warp-inclusive affine scan (5 shuffle steps) ----
        #pragma unroll
        for (int s = 1; s < 32; s <<= 1) {
            float Pu = __shfl_up_sync(0xFFFFFFFFu, P, s);
            float Qu = __shfl_up_sync(0xFFFFFFFFu, Q, s);
            if (lane >= s) { Q = fmaf(P, Qu, Q); P *= Pu; }
        }
        float LPe = __shfl_up_sync(0xFFFFFFFFu, P, 1);
        float LQe = __shfl_up_sync(0xFFFFFFFFu, Q, 1);
        if (lane == 0) { LPe = 1.0f; LQe = 0.0f; }
        float gt = fmaf(LPe, carry, LQe);

        float P31 = __shfl_sync(0xFFFFFFFFu, P, 31);
        float Q31 = __shfl_sync(0xFFFFFFFFu, Q, 31);
        carry = fmaf(P31, carry, Q31);

        // ---- fixup + coalesced stores ----
        float4 o0, o1;
        o0.x = fmaf(-dd[0], gt, ee[0]);
        o0.y = fmaf(-dd[1], gt, ee[1]);
        o0.z = fmaf(-dd[2], gt, ee[2]);
        o0.w = fmaf(-dd[3], gt, ee[3]);
        o1.x = fmaf(-dd[4], gt, ee[4]);
        o1.y = fmaf(-dd[5], gt, ee[5]);
        o1.z = fmaf(-dd[6], gt, ee[6]);
        o1.w = fmaf(-dd[7], gt, ee[7]);
        *reinterpret_cast<float4*>(out + off)     = o0;
        *reinterpret_cast<float4*>(out + off + 4) = o1;
        off += CHUNK;
    }
}

extern "C" void kernel_launch(void* const* d_in, const int* in_sizes, int n_in,
                              void* d_out, int out_size) {
    const float* eps = (const float*)d_in[0];
    const float* dt  = (const float*)d_in[1];
    float* out = (float*)d_out;

    maxwell_cpasync_kernel<<<GRID, TPB>>>(eps, dt, out);
}